// round 17
// baseline (speedup 1.0000x reference)
#include <cuda_runtime.h>
#include <cuda_bf16.h>
#include <cstdint>
#include <cstddef>

#define BSZ   32
#define TT    512
#define HH    512
#define G4    2048
#define GROUPS 4
#define GCTAS  32
#define BPG    8
#define NCTA  (GROUPS*GCTAS)
#define NTHR  512

// Device statics: byte-identical set to passing R13/R15/R16.
// g_xg is repurposed as the bf16 hi/lo h-exchange arena (no new statics!).
__device__ float g_xg[(size_t)TT * BSZ * G4];
__device__ float g_h[2][BSZ * HH];                // (declared, unused)
__device__ unsigned g_bar4[GROUPS * 32];          // per-group barrier counters

__device__ __forceinline__ float fast_sigmoid(float x) {
    return __fdividef(1.f, 1.f + __expf(-x));
}
__device__ __forceinline__ float fast_tanh(float x) {
    x = fminf(fmaxf(x, -15.f), 15.f);
    float e2 = __expf(-2.f * x);
    return __fdividef(1.f - e2, 1.f + e2);
}

__device__ __forceinline__ void mma_bf16(float4& c, const uint4& a, const uint2& b) {
    asm("mma.sync.aligned.m16n8k16.row.col.f32.bf16.bf16.f32 "
        "{%0,%1,%2,%3}, {%4,%5,%6,%7}, {%8,%9}, {%0,%1,%2,%3};"
        : "+f"(c.x), "+f"(c.y), "+f"(c.z), "+f"(c.w)
        : "r"(a.x), "r"(a.y), "r"(a.z), "r"(a.w), "r"(b.x), "r"(b.y));
}

__device__ __forceinline__ void split2(float2 v, unsigned& hi, unsigned& lo) {
    __nv_bfloat16 hx = __float2bfloat16(v.x);
    __nv_bfloat16 hy = __float2bfloat16(v.y);
    __nv_bfloat162 h = __halves2bfloat162(hx, hy);
    __nv_bfloat162 l = __halves2bfloat162(
        __float2bfloat16(v.x - __bfloat162float(hx)),
        __float2bfloat16(v.y - __bfloat162float(hy)));
    hi = *reinterpret_cast<unsigned*>(&h);
    lo = *reinterpret_cast<unsigned*>(&l);
}

// =====================================================================
// Fused LSTM kernel (R16 structure) with:
//  - earliest-possible barrier arrive (before x-staging)
//  - bf16 hi/lo h exchange via the g_xg arena
// =====================================================================
#define PSTR  260
#define WI_E  (64 * PSTR)
#define RED_RS    9
#define RED_PLANE 149
#define OFF_WIH 0
#define OFF_WIL (WI_E)
#define OFF_XSH (2 * WI_E)
#define OFF_XSL (2 * WI_E + 8 * PSTR)
#define OFF_HSH (2 * WI_E + 16 * PSTR)
#define OFF_HSL (2 * WI_E + 24 * PSTR)
#define OFF_RED (2 * WI_E + 32 * PSTR)
#define SMEM_UINTS (OFF_RED + 16 * RED_PLANE)
#define SMEM_REC_BYTES (SMEM_UINTS * 4)

#define HB_N (BSZ * HH)   // elems per buffer plane

__global__ void __launch_bounds__(512, 1) lstm_fused_kernel(
    const float* __restrict__ x,
    const float* __restrict__ Wih,
    const float* __restrict__ Whh,
    const float* __restrict__ bih,
    const float* __restrict__ bhh,
    float* __restrict__ out)
{
    extern __shared__ unsigned smu[];
    __shared__ unsigned tgt_s;
    unsigned* WiH = smu + OFF_WIH;
    unsigned* WiL = smu + OFF_WIL;
    unsigned* XsH = smu + OFF_XSH;
    unsigned* XsL = smu + OFF_XSL;
    unsigned* HsH = smu + OFF_HSH;
    unsigned* HsL = smu + OFF_HSL;
    float*    Red = reinterpret_cast<float*>(smu + OFF_RED);

    // bf16 h-exchange arena carved out of g_xg:
    //   plane 0/1: hi buffers (t&1), plane 2/3: lo buffers (t&1)
    __nv_bfloat16* hb = reinterpret_cast<__nv_bfloat16*>(g_xg);

    const int tid   = threadIdx.x;
    const int group = blockIdx.x >> 5;
    const int rank  = blockIdx.x & 31;
    const int B0    = group * BPG;
    const int J0    = rank * 16;
    const int wid   = tid >> 5;
    const int lane  = tid & 31;
    const int mg    = wid & 3;                  // gate tile (i,f,g,o)
    const int ks    = wid >> 2;                 // K-split 0..3
    const int gq    = lane >> 2;
    const int t4    = lane & 3;

    // ---- W_ih slice -> smem hi/lo pair-words ----
    for (int i = 0; i < 32; ++i) {
        int idx = tid + i * 512;
        int row = idx >> 8;
        int pp  = idx & 255;
        int g   = (row >> 4) * 512 + J0 + (row & 15);
        float2 v = *reinterpret_cast<const float2*>(&Wih[(size_t)g * 512 + pp * 2]);
        unsigned hi, lo;
        split2(v, hi, lo);
        WiH[row * PSTR + pp] = hi;
        WiL[row * PSTR + pp] = lo;
    }

    // ---- W_hh bf16x3 fragments -> registers ----
    uint4 wAH[8], wAL[8];
#pragma unroll
    for (int kk = 0; kk < 8; ++kk) {
        int cb = ks * 128 + kk * 16 + t4 * 2;
        int g1 = mg * 512 + J0 + gq;
        int g2 = g1 + 8;
        float2 v1a = *reinterpret_cast<const float2*>(&Whh[(size_t)g1 * 512 + cb]);
        float2 v2a = *reinterpret_cast<const float2*>(&Whh[(size_t)g2 * 512 + cb]);
        float2 v1b = *reinterpret_cast<const float2*>(&Whh[(size_t)g1 * 512 + cb + 8]);
        float2 v2b = *reinterpret_cast<const float2*>(&Whh[(size_t)g2 * 512 + cb + 8]);
        split2(v1a, wAH[kk].x, wAL[kk].x);
        split2(v2a, wAH[kk].y, wAL[kk].y);
        split2(v1b, wAH[kk].z, wAL[kk].z);
        split2(v2b, wAH[kk].w, wAL[kk].w);
    }

    const int gb = tid >> 4;
    const int jl = tid & 15;
    float c = 0.f;
    float bias0 = 0.f, bias1 = 0.f, bias2 = 0.f, bias3 = 0.f;
    if (tid < 128) {
        bias0 = bih[J0 + jl]        + bhh[J0 + jl];
        bias1 = bih[512 + J0 + jl]  + bhh[512 + J0 + jl];
        bias2 = bih[1024 + J0 + jl] + bhh[1024 + J0 + jl];
        bias3 = bih[1536 + J0 + jl] + bhh[1536 + J0 + jl];
    }

    unsigned* bp = &g_bar4[group * 32];
    __syncthreads();

    for (int t = 0; t < TT; ++t) {
        // ---- (E) already synced at loop entry; ARRIVE FIRST (t>0) ----
        if (t && tid == 0) {
            unsigned ticket;
            asm volatile("atom.release.gpu.add.u32 %0, [%1], %2;"
                         : "=r"(ticket) : "l"(bp), "r"(1u) : "memory");
            tgt_s = (ticket / (unsigned)GCTAS + 1u) * (unsigned)GCTAS;
        }

        // ---- stage x_t (overlaps peers' detection of our arrival) ----
#pragma unroll
        for (int i = 0; i < 4; ++i) {
            int p  = tid + i * 512;
            int b  = p >> 8;
            int pp = p & 255;
            float2 v = *reinterpret_cast<const float2*>(
                &x[((size_t)(B0 + b) * 512 + t) * 512 + pp * 2]);
            unsigned hi, lo;
            split2(v, hi, lo);
            XsH[b * PSTR + pp] = hi;
            XsL[b * PSTR + pp] = lo;
        }
        __syncthreads();        // (A) x staged

        // ---- x-mma: A = W_ih smem frags, B = x frags ----
        float4 acc = make_float4(0.f, 0.f, 0.f, 0.f);
#pragma unroll
        for (int kk = 0; kk < 8; ++kk) {
            int p0 = ks * 64 + kk * 8 + t4;
            int r1 = (mg * 16 + gq) * PSTR;
            int r2 = (mg * 16 + gq + 8) * PSTR;
            uint4 aH, aL;
            aH.x = WiH[r1 + p0]; aH.y = WiH[r2 + p0];
            aH.z = WiH[r1 + p0 + 4]; aH.w = WiH[r2 + p0 + 4];
            aL.x = WiL[r1 + p0]; aL.y = WiL[r2 + p0];
            aL.z = WiL[r1 + p0 + 4]; aL.w = WiL[r2 + p0 + 4];
            uint2 bH, bL;
            bH.x = XsH[gq * PSTR + p0];
            bH.y = XsH[gq * PSTR + p0 + 4];
            bL.x = XsL[gq * PSTR + p0];
            bL.y = XsL[gq * PSTR + p0 + 4];
            mma_bf16(acc, aH, bH);
            mma_bf16(acc, aH, bL);
            mma_bf16(acc, aL, bH);
        }

        if (t) {
            if (tid == 0) {
                unsigned target = tgt_s;
                unsigned cur;
                asm volatile("ld.acquire.gpu.u32 %0, [%1];"
                             : "=r"(cur) : "l"(bp) : "memory");
                while (cur < target) {
                    __nanosleep(32);
                    asm volatile("ld.acquire.gpu.u32 %0, [%1];"
                                 : "=r"(cur) : "l"(bp) : "memory");
                }
            }
            __syncthreads();    // (B) barrier passed

            // ---- stage h_{t-1}: pre-split bf16 hi/lo, direct uint copy ----
            const __nv_bfloat16* hH = hb + (size_t)((t + 1) & 1) * HB_N;
            const __nv_bfloat16* hL = hb + (size_t)(2 + ((t + 1) & 1)) * HB_N;
#pragma unroll
            for (int i = 0; i < 4; ++i) {
                int p  = tid + i * 512;
                int b  = p >> 8;
                int pp = p & 255;
                size_t gi = (size_t)(B0 + b) * 512 + pp * 2;
                HsH[b * PSTR + pp] = *reinterpret_cast<const unsigned*>(&hH[gi]);
                HsL[b * PSTR + pp] = *reinterpret_cast<const unsigned*>(&hL[gi]);
            }
        } else {
#pragma unroll
            for (int i = 0; i < 4; ++i) {
                int p  = tid + i * 512;
                int b  = p >> 8;
                int pp = p & 255;
                HsH[b * PSTR + pp] = 0u;
                HsL[b * PSTR + pp] = 0u;
            }
        }
        __syncthreads();        // (C) h staged

        // ---- h-mma into same acc ----
#pragma unroll
        for (int kk = 0; kk < 8; ++kk) {
            int p0 = ks * 64 + kk * 8 + t4;
            uint2 bH, bL;
            bH.x = HsH[gq * PSTR + p0];
            bH.y = HsH[gq * PSTR + p0 + 4];
            bL.x = HsL[gq * PSTR + p0];
            bL.y = HsL[gq * PSTR + p0 + 4];
            mma_bf16(acc, wAH[kk], bH);
            mma_bf16(acc, wAH[kk], bL);
            mma_bf16(acc, wAL[kk], bH);
        }
        {
            int plane = (mg * 4 + ks) * RED_PLANE;
            Red[plane + gq * RED_RS + t4 * 2]           = acc.x;
            Red[plane + gq * RED_RS + t4 * 2 + 1]       = acc.y;
            Red[plane + (gq + 8) * RED_RS + t4 * 2]     = acc.z;
            Red[plane + (gq + 8) * RED_RS + t4 * 2 + 1] = acc.w;
        }
        __syncthreads();        // (D) Red complete

        // ---- K-reduce + gates ----
        if (tid < 128) {
            float s[4];
#pragma unroll
            for (int m = 0; m < 4; ++m) {
                int off = jl * RED_RS + gb;
                s[m] = Red[(m * 4 + 0) * RED_PLANE + off]
                     + Red[(m * 4 + 1) * RED_PLANE + off]
                     + Red[(m * 4 + 2) * RED_PLANE + off]
                     + Red[(m * 4 + 3) * RED_PLANE + off];
            }
            float ig = fast_sigmoid(bias0 + s[0]);
            float fg = fast_sigmoid(bias1 + s[1]);
            float gg = fast_tanh(bias2 + s[2]);
            float og = fast_sigmoid(bias3 + s[3]);
            c = fg * c + ig * gg;
            float hval = og * fast_tanh(c);

            // h exchange: pre-split bf16 hi/lo stores
            size_t gi = (size_t)(B0 + gb) * 512 + J0 + jl;
            __nv_bfloat16 hhi = __float2bfloat16(hval);
            __nv_bfloat16 hlo = __float2bfloat16(hval - __bfloat162float(hhi));
            hb[(size_t)(t & 1) * HB_N + gi]       = hhi;
            hb[(size_t)(2 + (t & 1)) * HB_N + gi] = hlo;

            out[((size_t)(B0 + gb) * 512 + t) * 512 + J0 + jl] = fmaxf(hval, 0.f);
        }
        __syncthreads();        // (E) h writes fenced -> next-iter arrive legal
    }
}

extern "C" void kernel_launch(void* const* d_in, const int* in_sizes, int n_in,
                              void* d_out, int out_size)
{
    const float* x   = (const float*)d_in[0];
    const float* Wih = (const float*)d_in[1];
    const float* Whh = (const float*)d_in[2];
    const float* bih = (const float*)d_in[3];
    const float* bhh = (const float*)d_in[4];
    float* out = (float*)d_out;

    cudaFuncSetAttribute(lstm_fused_kernel,
                         cudaFuncAttributeMaxDynamicSharedMemorySize,
                         SMEM_REC_BYTES);
    lstm_fused_kernel<<<NCTA, NTHR, SMEM_REC_BYTES>>>(x, Wih, Whh, bih, bhh, out);
}